// round 8
// baseline (speedup 1.0000x reference)
#include <cuda_runtime.h>
#include <cuda_bf16.h>
#include <math.h>

// Problem constants (fixed by the reference)
#define BATCH     65536
#define EMBED_DIM 128
#define NEG_K     5

#define WARPS_PER_BLOCK 4
#define BLOCK_THREADS   (WARPS_PER_BLOCK * 32)   // 128
#define ELEMS_PER_WARP  2
#define CHUNK_ELEMS     (WARPS_PER_BLOCK * ELEMS_PER_WARP)   // 8
#define NCHUNKS         (BATCH / CHUNK_ELEMS)               // 8192
#define GRID_BLOCKS     912                      // 152 SMs x 6 resident blocks (persistent)

// Fixed-point packed accumulator+counter: low 48 bits = sum of
// round(block_sum * 2^24) [loss >= 0; total*2^24 ~ 4.6e12 << 2^48],
// bits [48:63] = arrival count (GRID_BLOCKS = 912 max). Integer adds are
// associative -> deterministic; the last-arriving block holds the complete
// total (old + own add) with no fences and no extra reads.
#define Q_SCALE     16777216.0            // 2^24
#define INV_Q_SCALE (1.0 / 16777216.0)
#define COUNT_SHIFT 48
#define COUNT_ONE   (1ULL << COUNT_SHIFT)
#define SUM_MASK    ((1ULL << COUNT_SHIFT) - 1ULL)

__device__ unsigned long long g_packed = 0ULL;

__device__ __forceinline__ float log_sigmoid(float x) {
    // stable: min(x,0) - log1p(exp(-|x|))
    return fminf(x, 0.0f) - log1pf(__expf(-fabsf(x)));
}

__device__ __forceinline__ float dot4(float4 a, float4 b) {
    return a.x * b.x + a.y * b.y + a.z * b.z + a.w * b.w;
}

__global__ __launch_bounds__(BLOCK_THREADS, 6)   // ~85 regs budget -> 6 blocks/SM
void skipgram_loss_kernel(const int* __restrict__ center,
                          const int* __restrict__ context,
                          const int* __restrict__ negatives,
                          const float* __restrict__ u_weight,
                          const float* __restrict__ v_weight,
                          float* __restrict__ out) {
    const int warp_in_block = threadIdx.x >> 5;
    const int lane          = threadIdx.x & 31;

    // per-lane local loss accumulators (only lanes 0/1 ever non-zero)
    float local = 0.0f;

    int g = blockIdx.x;

    // ---- load indices for the first chunk ----
    int ci0, ci1, xi0, xi1, n0[NEG_K], n1[NEG_K];
    {
        const int b0 = (g * WARPS_PER_BLOCK + warp_in_block) * ELEMS_PER_WARP;
        ci0 = center[b0];  ci1 = center[b0 + 1];
        xi0 = context[b0]; xi1 = context[b0 + 1];
        const int2* nv = reinterpret_cast<const int2*>(negatives + (size_t)b0 * NEG_K);
        int2 q0 = __ldg(nv + 0), q1 = __ldg(nv + 1), q2 = __ldg(nv + 2),
             q3 = __ldg(nv + 3), q4 = __ldg(nv + 4);
        n0[0] = q0.x; n0[1] = q0.y; n0[2] = q1.x; n0[3] = q1.y; n0[4] = q2.x;
        n1[0] = q2.y; n1[1] = q3.x; n1[2] = q3.y; n1[3] = q4.x; n1[4] = q4.y;
    }

    while (true) {
        // ---- issue all 14 row loads back-to-back ----
        float4 c40 = __ldg(reinterpret_cast<const float4*>(u_weight + (size_t)ci0 * EMBED_DIM) + lane);
        float4 c41 = __ldg(reinterpret_cast<const float4*>(u_weight + (size_t)ci1 * EMBED_DIM) + lane);
        float4 x40 = __ldg(reinterpret_cast<const float4*>(v_weight + (size_t)xi0 * EMBED_DIM) + lane);
        float4 x41 = __ldg(reinterpret_cast<const float4*>(v_weight + (size_t)xi1 * EMBED_DIM) + lane);
        float4 n40[NEG_K], n41[NEG_K];
#pragma unroll
        for (int k = 0; k < NEG_K; k++)
            n40[k] = __ldg(reinterpret_cast<const float4*>(v_weight + (size_t)n0[k] * EMBED_DIM) + lane);
#pragma unroll
        for (int k = 0; k < NEG_K; k++)
            n41[k] = __ldg(reinterpret_cast<const float4*>(v_weight + (size_t)n1[k] * EMBED_DIM) + lane);

        // ---- prefetch NEXT chunk's indices (hidden under the row-load latency) ----
        const int gn = g + GRID_BLOCKS;
        const bool have_next = (gn < NCHUNKS);
        int pci0 = 0, pci1 = 0, pxi0 = 0, pxi1 = 0, pn0[NEG_K], pn1[NEG_K];
        if (have_next) {
            const int b0 = (gn * WARPS_PER_BLOCK + warp_in_block) * ELEMS_PER_WARP;
            pci0 = center[b0];  pci1 = center[b0 + 1];
            pxi0 = context[b0]; pxi1 = context[b0 + 1];
            const int2* nv = reinterpret_cast<const int2*>(negatives + (size_t)b0 * NEG_K);
            int2 q0 = __ldg(nv + 0), q1 = __ldg(nv + 1), q2 = __ldg(nv + 2),
                 q3 = __ldg(nv + 3), q4 = __ldg(nv + 4);
            pn0[0] = q0.x; pn0[1] = q0.y; pn0[2] = q1.x; pn0[3] = q1.y; pn0[4] = q2.x;
            pn1[0] = q2.y; pn1[1] = q3.x; pn1[2] = q3.y; pn1[3] = q4.x; pn1[4] = q4.y;
        }

        // ---- 12 partial dots per lane ----
        float acc0[1 + NEG_K], acc1[1 + NEG_K];
        acc0[0] = dot4(c40, x40);
        acc1[0] = dot4(c41, x41);
#pragma unroll
        for (int k = 0; k < NEG_K; k++) {
            acc0[1 + k] = dot4(c40, n40[k]);
            acc1[1 + k] = dot4(c41, n41[k]);
        }

        // ---- butterfly warp reduction (ILP across 12 accumulators) ----
#pragma unroll
        for (int off = 16; off > 0; off >>= 1) {
#pragma unroll
            for (int j = 0; j < 1 + NEG_K; j++) {
                acc0[j] += __shfl_xor_sync(0xFFFFFFFFu, acc0[j], off);
                acc1[j] += __shfl_xor_sync(0xFFFFFFFFu, acc1[j], off);
            }
        }

        // ---- per-element losses: lane 0 -> elem0, lane 1 -> elem1 ----
        if (lane == 0) {
            float neg_loss = 0.0f;
#pragma unroll
            for (int k = 0; k < NEG_K; k++) neg_loss += log_sigmoid(-acc0[1 + k]);
            local += -(log_sigmoid(acc0[0]) + neg_loss);
        } else if (lane == 1) {
            float neg_loss = 0.0f;
#pragma unroll
            for (int k = 0; k < NEG_K; k++) neg_loss += log_sigmoid(-acc1[1 + k]);
            local += -(log_sigmoid(acc1[0]) + neg_loss);
        }

        if (!have_next) break;
        g = gn;
        ci0 = pci0; ci1 = pci1; xi0 = pxi0; xi1 = pxi1;
#pragma unroll
        for (int k = 0; k < NEG_K; k++) { n0[k] = pn0[k]; n1[k] = pn1[k]; }
    }

    // ---- combine lanes 0/1, then block-reduce, then ONE packed atomic ----
    local += __shfl_xor_sync(0xFFFFFFFFu, local, 1);   // lane 0: loss0+loss1 totals

    __shared__ float smem[WARPS_PER_BLOCK];
    if (lane == 0) smem[warp_in_block] = local;
    __syncthreads();

    if (threadIdx.x == 0) {
        float s = 0.0f;
#pragma unroll
        for (int w = 0; w < WARPS_PER_BLOCK; w++) s += smem[w];
        unsigned long long q = (unsigned long long)__double2ll_rn((double)s * Q_SCALE);
        unsigned long long my_add = COUNT_ONE + q;
        unsigned long long old = atomicAdd(&g_packed, my_add);
        if ((old >> COUNT_SHIFT) == (unsigned long long)(GRID_BLOCKS - 1)) {
            unsigned long long total = old + my_add;
            double sum = (double)(long long)(total & SUM_MASK) * INV_Q_SCALE;
            out[0] = (float)(sum / (double)BATCH);
            g_packed = 0ULL;   // reset for next graph replay (kernel-boundary ordered)
        }
    }
}

extern "C" void kernel_launch(void* const* d_in, const int* in_sizes, int n_in,
                              void* d_out, int out_size) {
    // metadata order: center_nodes, context_nodes, negative_nodes, u_weight, v_weight
    const int*   center    = (const int*)d_in[0];
    const int*   context   = (const int*)d_in[1];
    const int*   negatives = (const int*)d_in[2];
    const float* u_weight  = (const float*)d_in[3];
    const float* v_weight  = (const float*)d_in[4];
    float*       out       = (float*)d_out;

    skipgram_loss_kernel<<<GRID_BLOCKS, BLOCK_THREADS>>>(center, context, negatives,
                                                         u_weight, v_weight, out);
}